// round 1
// baseline (speedup 1.0000x reference)
#include <cuda_runtime.h>

// Problem constants (fixed by the reference: B=2, G=64)
constexpr int G3      = 64 * 64 * 64;   // 262144 voxels per batch
constexpr int NB      = 2;
constexpr int THREADS = 256;
constexpr int VEC     = 2;              // voxels per thread (float2 path)

// C_ijkl[b,v] = sum_{m,n,o,p} a[b,m,i,v] a[b,n,j,v] a[b,o,k,v] a[b,p,l,v] C0[m,n,o,p]
// computed as four staged rank-1 contractions (243 FMA each, 972 FMA total per voxel).
__global__ __launch_bounds__(THREADS)
void alphaC0_42C_kernel(const float* __restrict__ a,
                        const float* __restrict__ c0,
                        float* __restrict__ out)
{
    __shared__ float sc0[81];
    if (threadIdx.x < 81) sc0[threadIdx.x] = c0[threadIdx.x];
    __syncthreads();

    // Global pair index over the flattened (b, voxel) axis.
    // G3 is even, so a float2 pair never crosses the batch boundary.
    const long pair = (long)blockIdx.x * THREADS + threadIdx.x;
    const long v2   = pair * VEC;
    const int  b    = (int)(v2 / G3);
    const long v    = v2 - (long)b * G3;

    // Load the 3x3 per-voxel matrix a[m][i] for both voxels of the pair.
    // Layout: a[((b*3+m)*3+i)*G3 + v]  ->  A[m*3+i]
    const float* ap = a + (long)b * 9 * G3 + v;
    float2 A[9];
#pragma unroll
    for (int mi = 0; mi < 9; ++mi)
        A[mi] = *reinterpret_cast<const float2*>(ap + (long)mi * G3);

    float* ob = out + (long)b * 81 * G3 + v;

#pragma unroll
    for (int i = 0; i < 3; ++i) {
        // Stage 1: T1[n,o,p] = sum_m A[m,i] * C0[m,n,o,p]      (81 FMA-pairs)
        float2 T1[27];
#pragma unroll
        for (int nop = 0; nop < 27; ++nop) {
            float  c  = sc0[nop];              // m = 0
            float2 s;
            s.x = A[0 * 3 + i].x * c;
            s.y = A[0 * 3 + i].y * c;
            c = sc0[27 + nop];                 // m = 1
            s.x = fmaf(A[1 * 3 + i].x, c, s.x);
            s.y = fmaf(A[1 * 3 + i].y, c, s.y);
            c = sc0[54 + nop];                 // m = 2
            s.x = fmaf(A[2 * 3 + i].x, c, s.x);
            s.y = fmaf(A[2 * 3 + i].y, c, s.y);
            T1[nop] = s;
        }
#pragma unroll
        for (int j = 0; j < 3; ++j) {
            // Stage 2: T2[o,p] = sum_n A[n,j] * T1[n,o,p]
            float2 T2[9];
#pragma unroll
            for (int opq = 0; opq < 9; ++opq) {
                float2 s;
                s.x = A[0 * 3 + j].x * T1[opq].x;
                s.y = A[0 * 3 + j].y * T1[opq].y;
                s.x = fmaf(A[1 * 3 + j].x, T1[9 + opq].x, s.x);
                s.y = fmaf(A[1 * 3 + j].y, T1[9 + opq].y, s.y);
                s.x = fmaf(A[2 * 3 + j].x, T1[18 + opq].x, s.x);
                s.y = fmaf(A[2 * 3 + j].y, T1[18 + opq].y, s.y);
                T2[opq] = s;
            }
#pragma unroll
            for (int k = 0; k < 3; ++k) {
                // Stage 3: T3[p] = sum_o A[o,k] * T2[o,p]
                float2 T3[3];
#pragma unroll
                for (int p = 0; p < 3; ++p) {
                    float2 s;
                    s.x = A[0 * 3 + k].x * T2[p].x;
                    s.y = A[0 * 3 + k].y * T2[p].y;
                    s.x = fmaf(A[1 * 3 + k].x, T2[3 + p].x, s.x);
                    s.y = fmaf(A[1 * 3 + k].y, T2[3 + p].y, s.y);
                    s.x = fmaf(A[2 * 3 + k].x, T2[6 + p].x, s.x);
                    s.y = fmaf(A[2 * 3 + k].y, T2[6 + p].y, s.y);
                    T3[p] = s;
                }
#pragma unroll
                for (int l = 0; l < 3; ++l) {
                    // Stage 4: C[i,j,k,l] = sum_p A[p,l] * T3[p]
                    float2 r;
                    r.x = A[0 * 3 + l].x * T3[0].x;
                    r.y = A[0 * 3 + l].y * T3[0].y;
                    r.x = fmaf(A[1 * 3 + l].x, T3[1].x, r.x);
                    r.y = fmaf(A[1 * 3 + l].y, T3[1].y, r.y);
                    r.x = fmaf(A[2 * 3 + l].x, T3[2].x, r.x);
                    r.y = fmaf(A[2 * 3 + l].y, T3[2].y, r.y);
                    // C[b][i][j][k][l][v] — voxel index fastest => coalesced STG.64
                    *reinterpret_cast<float2*>(
                        ob + (long)(((i * 3 + j) * 3 + k) * 3 + l) * G3) = r;
                }
            }
        }
    }
}

extern "C" void kernel_launch(void* const* d_in, const int* in_sizes, int n_in,
                              void* d_out, int out_size)
{
    const float* a   = (const float*)d_in[0];   // alphatensor (2,3,3,64,64,64)
    const float* c0  = (const float*)d_in[1];   // C0_4 (3,3,3,3)
    float*       out = (float*)d_out;           // (2,3,3,3,3,64,64,64)

    const long total_pairs = (long)NB * G3 / VEC;          // 262144
    const int  blocks      = (int)(total_pairs / THREADS); // 1024
    alphaC0_42C_kernel<<<blocks, THREADS>>>(a, c0, out);
}